// round 7
// baseline (speedup 1.0000x reference)
#include <cuda_runtime.h>
#include <math.h>

#define T_STEPS 16384
#define IDIM 1024
#define HDIM 1024
#define GDIM 4096
#define NBLK 128
#define RTHREADS 256
#define NGRP 8                         // counter shards (one 128B line each)
#define WARPS_PER_GRP 128              // 16 CTAs * 8 warps

// ---------------- device globals (scratch; no allocations allowed) ------------
__device__ float g_xgates[(size_t)T_STEPS * GDIM];   // 256 MB input gates
__device__ __align__(16) float g_h[2][HDIM];         // double-buffered hidden state
__device__ unsigned g_ctr[NGRP * 32];                // 8 counters, 128B apart

// ---------------- packed f32x2 helpers ---------------------------------------
static __device__ __forceinline__ unsigned long long pk2(float lo, float hi) {
    unsigned long long r;
    asm("mov.b64 %0, {%1, %2};" : "=l"(r) : "f"(lo), "f"(hi));
    return r;
}
static __device__ __forceinline__ void fma2(unsigned long long& d,
                                            unsigned long long a,
                                            unsigned long long b) {
    asm("fma.rn.f32x2 %0, %1, %2, %0;" : "+l"(d) : "l"(a), "l"(b));
}
static __device__ __forceinline__ float2 up2(unsigned long long v) {
    float2 f;
    asm("mov.b64 {%0, %1}, %2;" : "=f"(f.x), "=f"(f.y) : "l"(v));
    return f;
}
static __device__ __forceinline__ float fast_sigmoid(float x) {
    return __fdividef(1.0f, 1.0f + __expf(-x));
}
static __device__ __forceinline__ float fast_tanh(float x) {
    return 1.0f - __fdividef(2.0f, __expf(2.0f * x) + 1.0f);
}
static __device__ __forceinline__ unsigned ld_acq(const unsigned* p) {
    unsigned v;
    asm volatile("ld.acquire.gpu.u32 %0, [%1];" : "=r"(v) : "l"(p) : "memory");
    return v;
}
static __device__ __forceinline__ void red_rel(unsigned* p) {
    asm volatile("red.release.gpu.add.u32 [%0], %1;" :: "l"(p), "r"(1u) : "memory");
}

// ---------------- init: reset counters each launch (graph replays!) -----------
__global__ void init_kernel() {
    int i = threadIdx.x;
    if (i < NGRP * 32) g_ctr[i] = 0u;
}

// ---------------- GEMM: x_gates = A @ W_ih^T + (b_ih + b_hh) ------------------
// (unchanged; proven in R1/R5)
__global__ __launch_bounds__(256) void gemm_kernel(
    const float* __restrict__ A, const float* __restrict__ W,
    const float* __restrict__ bih, const float* __restrict__ bhh) {
    __shared__ float As[8][132];
    __shared__ float Bs[8][132];

    const int tid = threadIdx.x;
    const int m0 = blockIdx.x * 128;
    const int n0 = blockIdx.y * 128;
    const int lrow = tid >> 1;
    const int kq = (tid & 1) * 4;
    const int tm = (tid & 15) * 8;
    const int tn = (tid >> 4) * 8;

    unsigned long long acc[4][8];
#pragma unroll
    for (int i = 0; i < 4; i++)
#pragma unroll
        for (int j = 0; j < 8; j++) acc[i][j] = 0ULL;

    const float* aptr = A + (size_t)(m0 + lrow) * IDIM + kq;
    const float* wptr = W + (size_t)(n0 + lrow) * IDIM + kq;

    float4 av = *(const float4*)aptr;
    float4 bv = *(const float4*)wptr;

    for (int k0 = 0; k0 < IDIM; k0 += 8) {
        __syncthreads();
        As[kq + 0][lrow] = av.x; As[kq + 1][lrow] = av.y;
        As[kq + 2][lrow] = av.z; As[kq + 3][lrow] = av.w;
        Bs[kq + 0][lrow] = bv.x; Bs[kq + 1][lrow] = bv.y;
        Bs[kq + 2][lrow] = bv.z; Bs[kq + 3][lrow] = bv.w;
        __syncthreads();
        if (k0 + 8 < IDIM) {
            av = *(const float4*)(aptr + k0 + 8);
            bv = *(const float4*)(wptr + k0 + 8);
        }
#pragma unroll
        for (int k = 0; k < 8; k++) {
            float4 a0 = *(const float4*)&As[k][tm];
            float4 a1 = *(const float4*)&As[k][tm + 4];
            float4 b0 = *(const float4*)&Bs[k][tn];
            float4 b1 = *(const float4*)&Bs[k][tn + 4];
            unsigned long long am[4] = { pk2(a0.x, a0.y), pk2(a0.z, a0.w),
                                         pk2(a1.x, a1.y), pk2(a1.z, a1.w) };
            float bb[8] = { b0.x, b0.y, b0.z, b0.w, b1.x, b1.y, b1.z, b1.w };
#pragma unroll
            for (int j = 0; j < 8; j++) {
                unsigned long long b2 = pk2(bb[j], bb[j]);
                fma2(acc[0][j], am[0], b2);
                fma2(acc[1][j], am[1], b2);
                fma2(acc[2][j], am[2], b2);
                fma2(acc[3][j], am[3], b2);
            }
        }
    }

    float bias[8];
#pragma unroll
    for (int j = 0; j < 8; j++) bias[j] = bih[n0 + tn + j] + bhh[n0 + tn + j];

#pragma unroll
    for (int i = 0; i < 4; i++) {
        float r0v[8], r1v[8];
#pragma unroll
        for (int j = 0; j < 8; j++) {
            float2 p = up2(acc[i][j]);
            r0v[j] = p.x + bias[j];
            r1v[j] = p.y + bias[j];
        }
        size_t row0 = (size_t)(m0 + tm + 2 * i) * GDIM + n0 + tn;
        size_t row1 = row0 + GDIM;
        *(float4*)&g_xgates[row0]     = make_float4(r0v[0], r0v[1], r0v[2], r0v[3]);
        *(float4*)&g_xgates[row0 + 4] = make_float4(r0v[4], r0v[5], r0v[6], r0v[7]);
        *(float4*)&g_xgates[row1]     = make_float4(r1v[0], r1v[1], r1v[2], r1v[3]);
        *(float4*)&g_xgates[row1 + 4] = make_float4(r1v[4], r1v[5], r1v[6], r1v[7]);
    }
}

// ---------------- persistent LSTM recurrence (warp-autonomous) ----------------
// 128 CTAs x 8 warps, zero __syncthreads in the loop. Warp w of CTA b owns
// h element e = b*8 + w. Per step each warp independently:
//   waits:    lanes 0..7 acquire-poll the 8 group counters until all >= 128*t
//             (ballot loop; nanosleep backoff after 4K probes)
//   loads:    lane l loads h[l + 32*j], j=0..31 (coalesced, matches weight map)
//   computes: 64 f32x2 FMAs -> 5-round shfl reduce
//   publishes:lane0 epilogue -> st.cg h[(t+1)&1][e] -> red.release +1.
// Safety: same release/acquire happens-before chain proven in R1/R5, at warp
// granularity: ctr[g] >= 128*t  <=>  every warp of group g finished step t-1.
// A warp overwrites buf[t&1] (writing h(t+2)) only after acquiring all of
// step t's releases, each program-ordered after that warp's reads of h(t).
// Liveness: all 128 CTAs are co-resident (<=148 SMs), counters are monotone.
__global__ __launch_bounds__(RTHREADS, 1) void lstm_kernel(const float* __restrict__ Whh) {
    const int tid = threadIdx.x;
    const int w = tid >> 5;             // warp 0..7
    const int lane = tid & 31;
    const int b = blockIdx.x;           // 0..127
    const int e = b * 8 + w;            // owned h element
    const int grp = b >> 4;             // this warp's arrival counter shard

    unsigned long long w01[32], w23[32];
#pragma unroll
    for (int c0 = 0; c0 < 32; c0++) {
        int col = lane + 32 * c0;
        w01[c0] = pk2(Whh[(size_t)(0 * HDIM + e) * HDIM + col],
                      Whh[(size_t)(1 * HDIM + e) * HDIM + col]);
        w23[c0] = pk2(Whh[(size_t)(2 * HDIM + e) * HDIM + col],
                      Whh[(size_t)(3 * HDIM + e) * HDIM + col]);
    }

    float c_state = 0.0f;               // lane 0's value is authoritative

    // Pre-load step 0's xg values (lane 0).
    float xg0, xg1, xg2, xg3;
    if (lane == 0) {
        const float* xr = &g_xgates[0 * (size_t)GDIM + e];
        xg0 = __ldcg(xr);
        xg1 = __ldcg(xr + HDIM);
        xg2 = __ldcg(xr + 2 * HDIM);
        xg3 = __ldcg(xr + 3 * HDIM);
    }

    for (int t = 0; t < T_STEPS; t++) {
        float hreg[32];
        if (t > 0) {
            const unsigned target = (unsigned)t * WARPS_PER_GRP;
            int probes = 0;
            for (;;) {
                unsigned v = target;
                if (lane < NGRP) v = ld_acq(&g_ctr[lane * 32]);
                if (__all_sync(0xffffffffu, v >= target)) break;
                if (++probes > 4096) __nanosleep(128);   // straggler backoff
            }
            const float* hb = g_h[t & 1];
#pragma unroll
            for (int j = 0; j < 32; j++)
                hreg[j] = __ldcg(hb + lane + 32 * j);
        } else {
#pragma unroll
            for (int j = 0; j < 32; j++) hreg[j] = 0.0f;
        }

        unsigned long long acc01 = 0ULL, acc23 = 0ULL;
#pragma unroll
        for (int j = 0; j < 32; j++) {
            unsigned long long hh = pk2(hreg[j], hreg[j]);
            fma2(acc01, w01[j], hh);
            fma2(acc23, w23[j], hh);
        }

        float2 s01 = up2(acc01), s23 = up2(acc23);
#pragma unroll
        for (int off = 16; off; off >>= 1) {
            s01.x += __shfl_xor_sync(0xffffffffu, s01.x, off);
            s01.y += __shfl_xor_sync(0xffffffffu, s01.y, off);
            s23.x += __shfl_xor_sync(0xffffffffu, s23.x, off);
            s23.y += __shfl_xor_sync(0xffffffffu, s23.y, off);
        }

        if (lane == 0) {
            float i_ = fast_sigmoid(s01.x + xg0);
            float f_ = fast_sigmoid(s01.y + xg1);
            float g_ = fast_tanh(s23.x + xg2);
            float o_ = fast_sigmoid(s23.y + xg3);
            c_state = f_ * c_state + i_ * g_;
            float hn = o_ * fast_tanh(c_state);
            __stcg(&g_h[(t + 1) & 1][e], hn);     // publish h(t+1)[e]
            red_rel(&g_ctr[grp * 32]);            // release: orders the store

            // Prefetch NEXT step's xg (off critical path: issued right after
            // release, consumed one full step later).
            if (t + 1 < T_STEPS) {
                const float* xr = &g_xgates[(size_t)(t + 1) * GDIM + e];
                xg0 = __ldcg(xr);
                xg1 = __ldcg(xr + HDIM);
                xg2 = __ldcg(xr + 2 * HDIM);
                xg3 = __ldcg(xr + 3 * HDIM);
            }
        }
    }
}

// ---------------- final: out = W_lin @ h_last + b_lin -------------------------
__global__ void final_kernel(const float* __restrict__ Wl,
                             const float* __restrict__ bl,
                             float* __restrict__ out) {
    __shared__ float partial[32];
    const int tid = threadIdx.x;     // 1024 threads
    float v = Wl[tid] * g_h[0][tid]; // h(T) lives in buffer (T_STEPS & 1) == 0
#pragma unroll
    for (int off = 16; off; off >>= 1) v += __shfl_xor_sync(0xffffffffu, v, off);
    if ((tid & 31) == 0) partial[tid >> 5] = v;
    __syncthreads();
    if (tid < 32) {
        float s = partial[tid];
#pragma unroll
        for (int off = 16; off; off >>= 1) s += __shfl_xor_sync(0xffffffffu, s, off);
        if (tid == 0) out[0] = s + bl[0];
    }
}

// ---------------- launch -------------------------------------------------------
extern "C" void kernel_launch(void* const* d_in, const int* in_sizes, int n_in,
                              void* d_out, int out_size) {
    const float* input = (const float*)d_in[0];   // [T, I]
    const float* W_ih  = (const float*)d_in[1];   // [4H, I]
    const float* W_hh  = (const float*)d_in[2];   // [4H, H]
    const float* b_ih  = (const float*)d_in[3];   // [4H]
    const float* b_hh  = (const float*)d_in[4];   // [4H]
    const float* W_lin = (const float*)d_in[5];   // [1, H]
    const float* b_lin = (const float*)d_in[6];   // [1]
    float* out = (float*)d_out;

    init_kernel<<<1, 256>>>();

    dim3 ggrid(T_STEPS / 128, GDIM / 128);        // (128, 32)
    gemm_kernel<<<ggrid, 256>>>(input, W_ih, b_ih, b_hh);

    lstm_kernel<<<NBLK, RTHREADS>>>(W_hh);

    final_kernel<<<1, 1024>>>(W_lin, b_lin, out);
}

// round 9
// speedup vs baseline: 2.3682x; 2.3682x over previous
#include <cuda_runtime.h>
#include <math.h>

#define T_STEPS 16384
#define IDIM 1024
#define HDIM 1024
#define GDIM 4096
#define NBLK 128
#define RTHREADS 256

// ---------------- device globals (scratch; no allocations allowed) ------------
__device__ float g_xgates[(size_t)T_STEPS * GDIM];   // 256 MB input gates
// h broadcast: slot i = u64 { lo: value bits, hi: tag = step }, double-buffered.
__device__ __align__(16) unsigned long long g_hp[2][HDIM];

// ---------------- packed f32x2 helpers ---------------------------------------
static __device__ __forceinline__ unsigned long long pk2(float lo, float hi) {
    unsigned long long r;
    asm("mov.b64 %0, {%1, %2};" : "=l"(r) : "f"(lo), "f"(hi));
    return r;
}
static __device__ __forceinline__ void fma2(unsigned long long& d,
                                            unsigned long long a,
                                            unsigned long long b) {
    asm("fma.rn.f32x2 %0, %1, %2, %0;" : "+l"(d) : "l"(a), "l"(b));
}
static __device__ __forceinline__ float2 up2(unsigned long long v) {
    float2 f;
    asm("mov.b64 {%0, %1}, %2;" : "=f"(f.x), "=f"(f.y) : "l"(v));
    return f;
}
static __device__ __forceinline__ float fast_sigmoid(float x) {
    return __fdividef(1.0f, 1.0f + __expf(-x));
}
static __device__ __forceinline__ float fast_tanh(float x) {
    return 1.0f - __fdividef(2.0f, __expf(2.0f * x) + 1.0f);
}
// MORALLY-STRONG 8B sync ops: single-copy atomic (no tearing — weak .cg b64 may
// legally split into 2x32b, the R2-R4 bug) and participate in causality order.
static __device__ __forceinline__ unsigned long long ld_acq64(const unsigned long long* p) {
    unsigned long long v;
    asm volatile("ld.acquire.gpu.b64 %0, [%1];" : "=l"(v) : "l"(p) : "memory");
    return v;
}
static __device__ __forceinline__ void st_rel64(unsigned long long* p, unsigned long long v) {
    asm volatile("st.release.gpu.b64 [%0], %1;" :: "l"(p), "l"(v) : "memory");
}
static __device__ __forceinline__ unsigned hi32(unsigned long long v) {
    return (unsigned)(v >> 32);
}
static __device__ __forceinline__ float lo32f(unsigned long long v) {
    return __uint_as_float((unsigned)v);
}

// ---------------- init: clear tags each launch (graph replays!) ---------------
__global__ void init_kernel() {
    int i = threadIdx.x + blockIdx.x * blockDim.x;   // 2048 threads
    if (i < 2 * HDIM) ((unsigned long long*)g_hp)[i] = 0ULL;  // tag 0
}

// ---------------- GEMM: x_gates = A @ W_ih^T + (b_ih + b_hh) ------------------
// (unchanged; proven R1/R5)
__global__ __launch_bounds__(256) void gemm_kernel(
    const float* __restrict__ A, const float* __restrict__ W,
    const float* __restrict__ bih, const float* __restrict__ bhh) {
    __shared__ float As[8][132];
    __shared__ float Bs[8][132];

    const int tid = threadIdx.x;
    const int m0 = blockIdx.x * 128;
    const int n0 = blockIdx.y * 128;
    const int lrow = tid >> 1;
    const int kq = (tid & 1) * 4;
    const int tm = (tid & 15) * 8;
    const int tn = (tid >> 4) * 8;

    unsigned long long acc[4][8];
#pragma unroll
    for (int i = 0; i < 4; i++)
#pragma unroll
        for (int j = 0; j < 8; j++) acc[i][j] = 0ULL;

    const float* aptr = A + (size_t)(m0 + lrow) * IDIM + kq;
    const float* wptr = W + (size_t)(n0 + lrow) * IDIM + kq;

    float4 av = *(const float4*)aptr;
    float4 bv = *(const float4*)wptr;

    for (int k0 = 0; k0 < IDIM; k0 += 8) {
        __syncthreads();
        As[kq + 0][lrow] = av.x; As[kq + 1][lrow] = av.y;
        As[kq + 2][lrow] = av.z; As[kq + 3][lrow] = av.w;
        Bs[kq + 0][lrow] = bv.x; Bs[kq + 1][lrow] = bv.y;
        Bs[kq + 2][lrow] = bv.z; Bs[kq + 3][lrow] = bv.w;
        __syncthreads();
        if (k0 + 8 < IDIM) {
            av = *(const float4*)(aptr + k0 + 8);
            bv = *(const float4*)(wptr + k0 + 8);
        }
#pragma unroll
        for (int k = 0; k < 8; k++) {
            float4 a0 = *(const float4*)&As[k][tm];
            float4 a1 = *(const float4*)&As[k][tm + 4];
            float4 b0 = *(const float4*)&Bs[k][tn];
            float4 b1 = *(const float4*)&Bs[k][tn + 4];
            unsigned long long am[4] = { pk2(a0.x, a0.y), pk2(a0.z, a0.w),
                                         pk2(a1.x, a1.y), pk2(a1.z, a1.w) };
            float bb[8] = { b0.x, b0.y, b0.z, b0.w, b1.x, b1.y, b1.z, b1.w };
#pragma unroll
            for (int j = 0; j < 8; j++) {
                unsigned long long b2 = pk2(bb[j], bb[j]);
                fma2(acc[0][j], am[0], b2);
                fma2(acc[1][j], am[1], b2);
                fma2(acc[2][j], am[2], b2);
                fma2(acc[3][j], am[3], b2);
            }
        }
    }

    float bias[8];
#pragma unroll
    for (int j = 0; j < 8; j++) bias[j] = bih[n0 + tn + j] + bhh[n0 + tn + j];

#pragma unroll
    for (int i = 0; i < 4; i++) {
        float r0v[8], r1v[8];
#pragma unroll
        for (int j = 0; j < 8; j++) {
            float2 p = up2(acc[i][j]);
            r0v[j] = p.x + bias[j];
            r1v[j] = p.y + bias[j];
        }
        size_t row0 = (size_t)(m0 + tm + 2 * i) * GDIM + n0 + tn;
        size_t row1 = row0 + GDIM;
        *(float4*)&g_xgates[row0]     = make_float4(r0v[0], r0v[1], r0v[2], r0v[3]);
        *(float4*)&g_xgates[row0 + 4] = make_float4(r0v[4], r0v[5], r0v[6], r0v[7]);
        *(float4*)&g_xgates[row1]     = make_float4(r1v[0], r1v[1], r1v[2], r1v[3]);
        *(float4*)&g_xgates[row1 + 4] = make_float4(r1v[4], r1v[5], r1v[6], r1v[7]);
    }
}

// ---------------- persistent LSTM recurrence ----------------------------------
// R5's proven CTA structure (smem h staging, warp-per-element compute, lane0
// epilogue) with sync+data MERGED: h slot = {value, tag} published by ONE
// st.release.gpu.b64; consumers acquire-poll their own 4 slots — a tag match
// delivers the value in the same access. One L2 round-trip per step, no
// atomics, no counters.
// Overwrite/skip safety: tag t+2 can enter buf[t&1] only after its producer
// acquired ALL tag-(t+1) slots, and each t+1 publication is ordered after its
// CTA's entire step-t poll (poll -> syncthreads -> compute -> syncthreads ->
// store). Hence no consumer can still be waiting on tag t when t+2 lands.
// Liveness: 128 CTAs co-resident (<=148 SMs); tags strictly advance.
__global__ __launch_bounds__(RTHREADS, 1) void lstm_kernel(const float* __restrict__ Whh) {
    __shared__ __align__(16) float sh_h[HDIM];

    const int tid = threadIdx.x;
    const int w = tid >> 5;             // warp 0..7
    const int lane = tid & 31;
    const int b = blockIdx.x;           // 0..127
    const int e = b * 8 + w;            // owned h element

    unsigned long long w01[32], w23[32];
#pragma unroll
    for (int c0 = 0; c0 < 32; c0++) {
        int col = lane + 32 * c0;
        w01[c0] = pk2(Whh[(size_t)(0 * HDIM + e) * HDIM + col],
                      Whh[(size_t)(1 * HDIM + e) * HDIM + col]);
        w23[c0] = pk2(Whh[(size_t)(2 * HDIM + e) * HDIM + col],
                      Whh[(size_t)(3 * HDIM + e) * HDIM + col]);
    }

    float c_state = 0.0f;               // lane 0's value is authoritative

    for (int t = 0; t < T_STEPS; t++) {
        // Prefetch this step's 4 xg values (lane 0; latency hides behind poll).
        float xg0, xg1, xg2, xg3;
        if (lane == 0) {
            const float* xr = &g_xgates[(size_t)t * GDIM + e];
            xg0 = __ldcg(xr);
            xg1 = __ldcg(xr + HDIM);
            xg2 = __ldcg(xr + 2 * HDIM);
            xg3 = __ldcg(xr + 3 * HDIM);
        }

        if (t > 0) {
            // Poll own 4 slots of h(t); per-slot early exit cuts L2 traffic.
            const unsigned long long* hb = g_hp[t & 1];
            const unsigned wtag = (unsigned)t;
            const unsigned long long* p0 = hb + 2 * tid;
            const unsigned long long* p1 = hb + 2 * tid + 1;
            const unsigned long long* p2 = hb + 512 + 2 * tid;
            const unsigned long long* p3 = hb + 513 + 2 * tid;
            unsigned long long v0 = 0, v1 = 0, v2 = 0, v3 = 0;
            bool d0 = false, d1 = false, d2 = false, d3 = false;
            int probes = 0;
            for (;;) {
                if (!d0) { v0 = ld_acq64(p0); d0 = (hi32(v0) == wtag); }
                if (!d1) { v1 = ld_acq64(p1); d1 = (hi32(v1) == wtag); }
                if (!d2) { v2 = ld_acq64(p2); d2 = (hi32(v2) == wtag); }
                if (!d3) { v3 = ld_acq64(p3); d3 = (hi32(v3) == wtag); }
                if (d0 && d1 && d2 && d3) break;
                if (++probes > 1024) __nanosleep(64);    // straggler backoff
            }
            sh_h[2 * tid]       = lo32f(v0);
            sh_h[2 * tid + 1]   = lo32f(v1);
            sh_h[512 + 2 * tid] = lo32f(v2);
            sh_h[513 + 2 * tid] = lo32f(v3);
        } else {
            ((float4*)sh_h)[tid] = make_float4(0.f, 0.f, 0.f, 0.f);
        }
        __syncthreads();

        unsigned long long acc01 = 0ULL, acc23 = 0ULL;
#pragma unroll
        for (int c0 = 0; c0 < 32; c0++) {
            float hv = sh_h[lane + 32 * c0];        // bank = lane: conflict-free
            unsigned long long hh = pk2(hv, hv);
            fma2(acc01, w01[c0], hh);
            fma2(acc23, w23[c0], hh);
        }
        __syncthreads();   // sh_h consumed; safe to refill next iteration

        float2 s01 = up2(acc01), s23 = up2(acc23);
#pragma unroll
        for (int off = 16; off; off >>= 1) {
            s01.x += __shfl_xor_sync(0xffffffffu, s01.x, off);
            s01.y += __shfl_xor_sync(0xffffffffu, s01.y, off);
            s23.x += __shfl_xor_sync(0xffffffffu, s23.x, off);
            s23.y += __shfl_xor_sync(0xffffffffu, s23.y, off);
        }

        if (lane == 0) {
            float i_ = fast_sigmoid(s01.x + xg0);
            float f_ = fast_sigmoid(s01.y + xg1);
            float g_ = fast_tanh(s23.x + xg2);
            float o_ = fast_sigmoid(s23.y + xg3);
            c_state = f_ * c_state + i_ * g_;
            float hn = o_ * fast_tanh(c_state);
            // Publish {value, tag t+1} in ONE morally-strong atomic 8B store.
            unsigned long long pv =
                ((unsigned long long)(unsigned)(t + 1) << 32) |
                (unsigned long long)__float_as_uint(hn);
            st_rel64(&g_hp[(t + 1) & 1][e], pv);
        }
    }
}

// ---------------- final: out = W_lin @ h_last + b_lin -------------------------
__global__ void final_kernel(const float* __restrict__ Wl,
                             const float* __restrict__ bl,
                             float* __restrict__ out) {
    __shared__ float partial[32];
    const int tid = threadIdx.x;     // 1024 threads
    // h(T) lives in buffer (T_STEPS & 1) == 0, tag T_STEPS.
    float v = Wl[tid] * lo32f(g_hp[0][tid]);
#pragma unroll
    for (int off = 16; off; off >>= 1) v += __shfl_xor_sync(0xffffffffu, v, off);
    if ((tid & 31) == 0) partial[tid >> 5] = v;
    __syncthreads();
    if (tid < 32) {
        float s = partial[tid];
#pragma unroll
        for (int off = 16; off; off >>= 1) s += __shfl_xor_sync(0xffffffffu, s, off);
        if (tid == 0) out[0] = s + bl[0];
    }
}

// ---------------- launch -------------------------------------------------------
extern "C" void kernel_launch(void* const* d_in, const int* in_sizes, int n_in,
                              void* d_out, int out_size) {
    const float* input = (const float*)d_in[0];   // [T, I]
    const float* W_ih  = (const float*)d_in[1];   // [4H, I]
    const float* W_hh  = (const float*)d_in[2];   // [4H, H]
    const float* b_ih  = (const float*)d_in[3];   // [4H]
    const float* b_hh  = (const float*)d_in[4];   // [4H]
    const float* W_lin = (const float*)d_in[5];   // [1, H]
    const float* b_lin = (const float*)d_in[6];   // [1]
    float* out = (float*)d_out;

    init_kernel<<<8, 256>>>();

    dim3 ggrid(T_STEPS / 128, GDIM / 128);        // (128, 32)
    gemm_kernel<<<ggrid, 256>>>(input, W_ih, b_ih, b_hh);

    lstm_kernel<<<NBLK, RTHREADS>>>(W_hh);

    final_kernel<<<1, 1024>>>(W_lin, b_lin, out);
}